// round 1
// baseline (speedup 1.0000x reference)
#include <cuda_runtime.h>

// Transposed (channel-contiguous) feature scratch for the selected batch.
// Sizes: 56*56*64 + 28*28*128 + 14*14*256 + 7*7*512 = 376,832 floats (~1.5 MB).
__device__ float g_f0[56 * 56 * 64];
__device__ float g_f1[28 * 28 * 128];
__device__ float g_f2[14 * 14 * 256];
__device__ float g_f3[7 * 7 * 512];

// ---------------------------------------------------------------------------
// Prep: transpose feat[batch] from [C,S,S] to [S,S,C] so per-point gathers are
// contiguous C-length vectors. Tiny (1.5 MB), grid-stride over each level.
// ---------------------------------------------------------------------------
__device__ __forceinline__ void transpose_level(const float* __restrict__ src,
                                                float* __restrict__ dst,
                                                int C, int SS, int tid, int stride) {
    int total = C * SS;
    for (int i = tid; i < total; i += stride) {
        int c = i / SS;
        int p = i - c * SS;
        dst[p * C + c] = src[i];
    }
}

__global__ void transpose_all_kernel(const float* __restrict__ f0,
                                     const float* __restrict__ f1,
                                     const float* __restrict__ f2,
                                     const float* __restrict__ f3,
                                     const int* __restrict__ batch_p) {
    int b = *batch_p;
    int tid = blockIdx.x * blockDim.x + threadIdx.x;
    int stride = gridDim.x * blockDim.x;
    transpose_level(f0 + (size_t)b * 64 * 56 * 56, g_f0, 64, 56 * 56, tid, stride);
    transpose_level(f1 + (size_t)b * 128 * 28 * 28, g_f1, 128, 28 * 28, tid, stride);
    transpose_level(f2 + (size_t)b * 256 * 14 * 14, g_f2, 256, 14 * 14, tid, stride);
    transpose_level(f3 + (size_t)b * 512 * 7 * 7, g_f3, 512, 7 * 7, tid, stride);
}

// ---------------------------------------------------------------------------
// Main: one warp per point. The reference's truncated-weight bilinear reduces
// to: out_row = (x non-integer && below edge && same for y) ? feat[:,x1,y1] : 0
// ---------------------------------------------------------------------------
template <int S, int C, int OFF>
__device__ __forceinline__ void do_level(const float* __restrict__ fbuf,
                                         float* __restrict__ outrow,
                                         float h, float w, int lane) {
    constexpr float scale = (float)S / 224.0f;  // exact power of two (1/4..1/32)
    float x = x = h * scale;
    float y = w * scale;
    int x1 = (int)floorf(x);
    int x2 = min((int)ceilf(x), S - 1);
    int y1 = (int)floorf(y);
    int y2 = min((int)ceilf(y), S - 1);
    bool wt = (x2 > x1) && (y2 > y1);

    float4* dst = (float4*)(outrow + OFF);
    constexpr int N4 = C / 4;               // 16, 32, 64, 128
    constexpr int FULL = N4 / 32;           // full warp-wide float4 iterations
    constexpr int REM = N4 - FULL * 32;     // remainder lanes

    if (wt) {
        const float4* src = (const float4*)(fbuf + (x1 * S + y1) * C);
#pragma unroll
        for (int i = 0; i < FULL; i++)
            dst[lane + 32 * i] = __ldg(&src[lane + 32 * i]);
        if (REM > 0 && lane < REM)
            dst[FULL * 32 + lane] = __ldg(&src[FULL * 32 + lane]);
    } else {
        const float4 z = make_float4(0.f, 0.f, 0.f, 0.f);
#pragma unroll
        for (int i = 0; i < FULL; i++)
            dst[lane + 32 * i] = z;
        if (REM > 0 && lane < REM)
            dst[FULL * 32 + lane] = z;
    }
}

__global__ __launch_bounds__(256) void proj_kernel(const float* __restrict__ pts,
                                                   float* __restrict__ out,
                                                   int N) {
    int warp = (blockIdx.x * blockDim.x + threadIdx.x) >> 5;
    int lane = threadIdx.x & 31;
    if (warp >= N) return;

    float px = __ldg(&pts[warp * 3 + 0]);
    float py = __ldg(&pts[warp * 3 + 1]);
    float pz = __ldg(&pts[warp * 3 + 2]);

    // Match XLA's rounding exactly: no FMA contraction.
    float h = __fadd_rn(__fmul_rn(248.0f, __fdiv_rn(py, pz)), 111.5f);
    float w = __fadd_rn(__fmul_rn(248.0f, __fdiv_rn(px, -pz)), 111.5f);
    h = fminf(fmaxf(h, 0.0f), 223.0f);
    w = fminf(fmaxf(w, 0.0f), 223.0f);

    float* outrow = out + (size_t)warp * 960;
    do_level<56, 64, 0>(g_f0, outrow, h, w, lane);
    do_level<28, 128, 64>(g_f1, outrow, h, w, lane);
    do_level<14, 256, 192>(g_f2, outrow, h, w, lane);
    do_level<7, 512, 448>(g_f3, outrow, h, w, lane);
}

extern "C" void kernel_launch(void* const* d_in, const int* in_sizes, int n_in,
                              void* d_out, int out_size) {
    const float* f0 = (const float*)d_in[0];
    const float* f1 = (const float*)d_in[1];
    const float* f2 = (const float*)d_in[2];
    const float* f3 = (const float*)d_in[3];
    const float* pts = (const float*)d_in[4];
    const int* batch = (const int*)d_in[5];

    int N = in_sizes[4] / 3;  // number of points

    // Prep transpose: 376,832 elements, grid-stride.
    transpose_all_kernel<<<592, 256>>>(f0, f1, f2, f3, batch);

    // Main: one warp per point.
    int total_threads = N * 32;
    int blocks = (total_threads + 255) / 256;
    proj_kernel<<<blocks, 256>>>(pts, (float*)d_out, N);
}

// round 2
// speedup vs baseline: 1.2841x; 1.2841x over previous
#include <cuda_runtime.h>

// Transposed (channel-contiguous) feature scratch for the selected batch.
// 56*56*64 + 28*28*128 + 14*14*256 + 7*7*512 = 376,832 floats (~1.5 MB).
__device__ float g_f0[56 * 56 * 64];
__device__ float g_f1[28 * 28 * 128];
__device__ float g_f2[14 * 14 * 256];
__device__ float g_f3[7 * 7 * 512];

// ---------------------------------------------------------------------------
// Prep: transpose feat[batch] from [C,S,S] to [S,S,C]. Coalesced reads of the
// cold DRAM data; strided writes land in L2 (scratch is L2-resident).
// ---------------------------------------------------------------------------
__device__ __forceinline__ void transpose_level(const float* __restrict__ src,
                                                float* __restrict__ dst,
                                                int C, int SS, int tid, int stride) {
    int total = C * SS;
    for (int i = tid; i < total; i += stride) {
        int c = i / SS;
        int p = i - c * SS;
        dst[p * C + c] = src[i];
    }
}

__global__ void transpose_all_kernel(const float* __restrict__ f0,
                                     const float* __restrict__ f1,
                                     const float* __restrict__ f2,
                                     const float* __restrict__ f3,
                                     const int* __restrict__ batch_p) {
    int b = *batch_p;
    int tid = blockIdx.x * blockDim.x + threadIdx.x;
    int stride = gridDim.x * blockDim.x;
    transpose_level(f0 + (size_t)b * 64 * 56 * 56, g_f0, 64, 56 * 56, tid, stride);
    transpose_level(f1 + (size_t)b * 128 * 28 * 28, g_f1, 128, 28 * 28, tid, stride);
    transpose_level(f2 + (size_t)b * 256 * 14 * 14, g_f2, 256, 14 * 14, tid, stride);
    transpose_level(f3 + (size_t)b * 512 * 7 * 7, g_f3, 512, 7 * 7, tid, stride);
}

// ---------------------------------------------------------------------------
// Per-level packed offset: the reference's truncated bilinear weights are
// integer; only w11=(x2-x1)*(y2-y1) can be nonzero, and it is 0 or 1.
// Returns (x1*S+y1)*C when weight==1, else -1 (row is zeros).
// ---------------------------------------------------------------------------
template <int S, int C>
__device__ __forceinline__ int level_offset(float h, float w) {
    constexpr float scale = (float)S / 224.0f;  // exact power of two
    float x = h * scale;
    float y = w * scale;
    int x1 = (int)floorf(x);
    int x2 = min((int)ceilf(x), S - 1);
    int y1 = (int)floorf(y);
    int y2 = min((int)ceilf(y), S - 1);
    return ((x2 > x1) && (y2 > y1)) ? (x1 * S + y1) * C : -1;
}

// Emit one level's C channels for one point. Warp-cooperative, float4.
template <int C, int OFF>
__device__ __forceinline__ void emit(const float* __restrict__ fbuf,
                                     float* __restrict__ outrow,
                                     int off, int lane) {
    float4* dst = (float4*)(outrow + OFF);
    constexpr int N4 = C / 4;            // 16, 32, 64, 128
    constexpr int FULL = N4 / 32;        // warp-wide float4 iterations
    constexpr int REM = N4 - FULL * 32;  // remainder lanes

    if (off >= 0) {
        const float4* src = (const float4*)(fbuf + off);
#pragma unroll
        for (int i = 0; i < FULL; i++)
            __stcs(&dst[lane + 32 * i], __ldg(&src[lane + 32 * i]));
        if (REM > 0 && lane < REM)
            __stcs(&dst[FULL * 32 + lane], __ldg(&src[FULL * 32 + lane]));
    } else {
        const float4 z = make_float4(0.f, 0.f, 0.f, 0.f);
#pragma unroll
        for (int i = 0; i < FULL; i++)
            __stcs(&dst[lane + 32 * i], z);
        if (REM > 0 && lane < REM)
            __stcs(&dst[FULL * 32 + lane], z);
    }
}

// ---------------------------------------------------------------------------
// Main: each warp handles PTS_PER_WARP consecutive points. Lanes 0..15 compute
// their own point's offsets; the warp then streams all 16 rows.
// ---------------------------------------------------------------------------
constexpr int PTS_PER_WARP = 16;

__global__ __launch_bounds__(256) void proj_kernel(const float* __restrict__ pts,
                                                   float* __restrict__ out,
                                                   int N) {
    int warp = (blockIdx.x * blockDim.x + threadIdx.x) >> 5;
    int lane = threadIdx.x & 31;
    int base = warp * PTS_PER_WARP;
    if (base >= N) return;

    // Each of lanes 0..15 computes offsets for its own point.
    int o0 = -1, o1 = -1, o2 = -1, o3 = -1;
    int mypt = base + lane;
    if (lane < PTS_PER_WARP && mypt < N) {
        float px = __ldg(&pts[mypt * 3 + 0]);
        float py = __ldg(&pts[mypt * 3 + 1]);
        float pz = __ldg(&pts[mypt * 3 + 2]);
        // Match XLA rounding exactly: no FMA contraction.
        float h = __fadd_rn(__fmul_rn(248.0f, __fdiv_rn(py, pz)), 111.5f);
        float w = __fadd_rn(__fmul_rn(248.0f, __fdiv_rn(px, -pz)), 111.5f);
        h = fminf(fmaxf(h, 0.0f), 223.0f);
        w = fminf(fmaxf(w, 0.0f), 223.0f);
        o0 = level_offset<56, 64>(h, w);
        o1 = level_offset<28, 128>(h, w);
        o2 = level_offset<14, 256>(h, w);
        o3 = level_offset<7, 512>(h, w);
    }

#pragma unroll 4
    for (int i = 0; i < PTS_PER_WARP; i++) {
        int p = base + i;
        if (p >= N) break;
        float* outrow = out + (size_t)p * 960;
        int q0 = __shfl_sync(0xFFFFFFFFu, o0, i);
        int q1 = __shfl_sync(0xFFFFFFFFu, o1, i);
        int q2 = __shfl_sync(0xFFFFFFFFu, o2, i);
        int q3 = __shfl_sync(0xFFFFFFFFu, o3, i);
        emit<64, 0>(g_f0, outrow, q0, lane);
        emit<128, 64>(g_f1, outrow, q1, lane);
        emit<256, 192>(g_f2, outrow, q2, lane);
        emit<512, 448>(g_f3, outrow, q3, lane);
    }
}

extern "C" void kernel_launch(void* const* d_in, const int* in_sizes, int n_in,
                              void* d_out, int out_size) {
    const float* f0 = (const float*)d_in[0];
    const float* f1 = (const float*)d_in[1];
    const float* f2 = (const float*)d_in[2];
    const float* f3 = (const float*)d_in[3];
    const float* pts = (const float*)d_in[4];
    const int* batch = (const int*)d_in[5];

    int N = in_sizes[4] / 3;  // number of points

    transpose_all_kernel<<<592, 256>>>(f0, f1, f2, f3, batch);

    int warps = (N + PTS_PER_WARP - 1) / PTS_PER_WARP;
    int blocks = (warps * 32 + 255) / 256;
    proj_kernel<<<blocks, 256>>>(pts, (float*)d_out, N);
}

// round 6
// speedup vs baseline: 1.3594x; 1.0586x over previous
#include <cuda_runtime.h>

// Transposed (channel-contiguous) feature scratch for the selected batch.
// 56*56*64 + 28*28*128 + 14*14*256 + 7*7*512 = 376,832 floats (~1.5 MB).
__device__ float g_f0[56 * 56 * 64];
__device__ float g_f1[28 * 28 * 128];
__device__ float g_f2[14 * 14 * 256];
__device__ float g_f3[7 * 7 * 512];

// ---------------------------------------------------------------------------
// Tiled transpose: src [C, SS] -> dst [SS, C], 32x32 SMEM tiles so both the
// DRAM reads and the scratch writes are fully coalesced (8x fewer sectors
// than the naive strided version).
// ---------------------------------------------------------------------------
template <int C, int SS>
__device__ __forceinline__ void ttile(const float* __restrict__ src,
                                      float* __restrict__ dst, int bid,
                                      float (*t)[33]) {
    constexpr int TP = (SS + 31) / 32;
    int pt = bid % TP;
    int ct = bid / TP;
    int p0 = pt * 32, c0 = ct * 32;
    int tx = threadIdx.x, ty = threadIdx.y;  // 32 x 8

#pragma unroll
    for (int j = 0; j < 32; j += 8) {
        int c = c0 + ty + j, p = p0 + tx;
        if (c < C && p < SS) t[ty + j][tx] = src[c * SS + p];
    }
    __syncthreads();
#pragma unroll
    for (int j = 0; j < 32; j += 8) {
        int p = p0 + ty + j, c = c0 + tx;
        if (c < C && p < SS) dst[p * C + c] = t[tx][ty + j];
    }
}

// Tile counts: L0: ceil(3136/32)*ceil(64/32)=98*2=196; L1: 25*4=100;
// L2: 7*8=56; L3: 2*16=32. Total 384 blocks.
__global__ void transpose_all_kernel(const float* __restrict__ f0,
                                     const float* __restrict__ f1,
                                     const float* __restrict__ f2,
                                     const float* __restrict__ f3,
                                     const int* __restrict__ batch_p) {
    __shared__ float t[32][33];
    int b = *batch_p;
    int bid = blockIdx.x;
    if (bid < 196) {
        ttile<64, 3136>(f0 + (size_t)b * 64 * 3136, g_f0, bid, t);
    } else if (bid < 296) {
        ttile<128, 784>(f1 + (size_t)b * 128 * 784, g_f1, bid - 196, t);
    } else if (bid < 352) {
        ttile<256, 196>(f2 + (size_t)b * 256 * 196, g_f2, bid - 296, t);
    } else {
        ttile<512, 49>(f3 + (size_t)b * 512 * 49, g_f3, bid - 352, t);
    }
}

// ---------------------------------------------------------------------------
// Per-level packed offset: the reference's truncated bilinear weights are
// integer; only w11=(x2-x1)*(y2-y1) can be nonzero, and it is 0 or 1.
// Returns (x1*S+y1)*C when weight==1, else -1 (row is zeros).
// ---------------------------------------------------------------------------
template <int S, int C>
__device__ __forceinline__ int level_offset(float h, float w) {
    constexpr float scale = (float)S / 224.0f;  // exact power of two
    float x = h * scale;
    float y = w * scale;
    int x1 = (int)floorf(x);
    int x2 = min((int)ceilf(x), S - 1);
    int y1 = (int)floorf(y);
    int y2 = min((int)ceilf(y), S - 1);
    return ((x2 > x1) && (y2 > y1)) ? (x1 * S + y1) * C : -1;
}

// Emit one level's C channels for one point. Warp-cooperative, float4,
// streaming stores (output never re-read; keep L2 for the feature scratch).
template <int C, int OFF>
__device__ __forceinline__ void emit(const float* __restrict__ fbuf,
                                     float* __restrict__ outrow,
                                     int off, int lane) {
    float4* dst = (float4*)(outrow + OFF);
    constexpr int N4 = C / 4;            // 16, 32, 64, 128
    constexpr int FULL = N4 / 32;        // warp-wide float4 iterations
    constexpr int REM = N4 - FULL * 32;  // remainder lanes

    if (off >= 0) {
        const float4* src = (const float4*)(fbuf + off);
#pragma unroll
        for (int i = 0; i < FULL; i++)
            __stcs(&dst[lane + 32 * i], __ldg(&src[lane + 32 * i]));
        if (REM > 0 && lane < REM)
            __stcs(&dst[FULL * 32 + lane], __ldg(&src[FULL * 32 + lane]));
    } else {
        const float4 z = make_float4(0.f, 0.f, 0.f, 0.f);
#pragma unroll
        for (int i = 0; i < FULL; i++)
            __stcs(&dst[lane + 32 * i], z);
        if (REM > 0 && lane < REM)
            __stcs(&dst[FULL * 32 + lane], z);
    }
}

// ---------------------------------------------------------------------------
// Main: each warp handles PTS_PER_WARP consecutive points. Lanes 0..7 compute
// their own point's offsets; the warp then streams the 8 rows back-to-back.
// ---------------------------------------------------------------------------
constexpr int PTS_PER_WARP = 8;

__global__ __launch_bounds__(256) void proj_kernel(const float* __restrict__ pts,
                                                   float* __restrict__ out,
                                                   int N) {
    int warp = (blockIdx.x * blockDim.x + threadIdx.x) >> 5;
    int lane = threadIdx.x & 31;
    int base = warp * PTS_PER_WARP;
    if (base >= N) return;

    // Each of lanes 0..7 computes offsets for its own point.
    int o0 = -1, o1 = -1, o2 = -1, o3 = -1;
    int mypt = base + lane;
    if (lane < PTS_PER_WARP && mypt < N) {
        float px = __ldg(&pts[mypt * 3 + 0]);
        float py = __ldg(&pts[mypt * 3 + 1]);
        float pz = __ldg(&pts[mypt * 3 + 2]);
        // Match XLA rounding exactly: no FMA contraction.
        float h = __fadd_rn(__fmul_rn(248.0f, __fdiv_rn(py, pz)), 111.5f);
        float w = __fadd_rn(__fmul_rn(248.0f, __fdiv_rn(px, -pz)), 111.5f);
        h = fminf(fmaxf(h, 0.0f), 223.0f);
        w = fminf(fmaxf(w, 0.0f), 223.0f);
        o0 = level_offset<56, 64>(h, w);
        o1 = level_offset<28, 128>(h, w);
        o2 = level_offset<14, 256>(h, w);
        o3 = level_offset<7, 512>(h, w);
    }

#pragma unroll
    for (int i = 0; i < PTS_PER_WARP; i++) {
        int p = base + i;
        if (p >= N) break;
        float* outrow = out + (size_t)p * 960;
        int q0 = __shfl_sync(0xFFFFFFFFu, o0, i);
        int q1 = __shfl_sync(0xFFFFFFFFu, o1, i);
        int q2 = __shfl_sync(0xFFFFFFFFu, o2, i);
        int q3 = __shfl_sync(0xFFFFFFFFu, o3, i);
        emit<64, 0>(g_f0, outrow, q0, lane);
        emit<128, 64>(g_f1, outrow, q1, lane);
        emit<256, 192>(g_f2, outrow, q2, lane);
        emit<512, 448>(g_f3, outrow, q3, lane);
    }
}

extern "C" void kernel_launch(void* const* d_in, const int* in_sizes, int n_in,
                              void* d_out, int out_size) {
    const float* f0 = (const float*)d_in[0];
    const float* f1 = (const float*)d_in[1];
    const float* f2 = (const float*)d_in[2];
    const float* f3 = (const float*)d_in[3];
    const float* pts = (const float*)d_in[4];
    const int* batch = (const int*)d_in[5];

    int N = in_sizes[4] / 3;  // number of points

    dim3 tblock(32, 8);
    transpose_all_kernel<<<384, tblock>>>(f0, f1, f2, f3, batch);

    int warps = (N + PTS_PER_WARP - 1) / PTS_PER_WARP;
    int blocks = (warps * 32 + 255) / 256;
    proj_kernel<<<blocks, 256>>>(pts, (float*)d_out, N);
}

// round 7
// speedup vs baseline: 1.3859x; 1.0195x over previous
#include <cuda_runtime.h>

// Transposed (channel-contiguous) feature scratch for the selected batch.
// 56*56*64 + 28*28*128 + 14*14*256 + 7*7*512 = 376,832 floats (~1.5 MB).
__device__ float g_f0[56 * 56 * 64];
__device__ float g_f1[28 * 28 * 128];
__device__ float g_f2[14 * 14 * 256];
__device__ float g_f3[7 * 7 * 512];

// ---------------------------------------------------------------------------
// Tiled transpose: src [C, SS] -> dst [SS, C], 32x32 SMEM tiles so both the
// DRAM reads and the scratch writes are fully coalesced.
// ---------------------------------------------------------------------------
template <int C, int SS>
__device__ __forceinline__ void ttile(const float* __restrict__ src,
                                      float* __restrict__ dst, int bid,
                                      float (*t)[33]) {
    constexpr int TP = (SS + 31) / 32;
    int pt = bid % TP;
    int ct = bid / TP;
    int p0 = pt * 32, c0 = ct * 32;
    int tx = threadIdx.x, ty = threadIdx.y;  // 32 x 8

#pragma unroll
    for (int j = 0; j < 32; j += 8) {
        int c = c0 + ty + j, p = p0 + tx;
        if (c < C && p < SS) t[ty + j][tx] = src[c * SS + p];
    }
    __syncthreads();
#pragma unroll
    for (int j = 0; j < 32; j += 8) {
        int p = p0 + ty + j, c = c0 + tx;
        if (c < C && p < SS) dst[p * C + c] = t[tx][ty + j];
    }
}

// Tile counts: L0: 98*2=196; L1: 25*4=100; L2: 7*8=56; L3: 2*16=32. Sum 384.
__global__ void transpose_all_kernel(const float* __restrict__ f0,
                                     const float* __restrict__ f1,
                                     const float* __restrict__ f2,
                                     const float* __restrict__ f3,
                                     const int* __restrict__ batch_p) {
    __shared__ float t[32][33];
    int b = *batch_p;
    int bid = blockIdx.x;
    if (bid < 196) {
        ttile<64, 3136>(f0 + (size_t)b * 64 * 3136, g_f0, bid, t);
    } else if (bid < 296) {
        ttile<128, 784>(f1 + (size_t)b * 128 * 784, g_f1, bid - 196, t);
    } else if (bid < 352) {
        ttile<256, 196>(f2 + (size_t)b * 256 * 196, g_f2, bid - 296, t);
    } else {
        ttile<512, 49>(f3 + (size_t)b * 512 * 49, g_f3, bid - 352, t);
    }
#if __CUDA_ARCH__ >= 900
    cudaTriggerProgrammaticLaunchCompletion();
#endif
}

// ---------------------------------------------------------------------------
// Per-level packed offset: the reference's truncated bilinear weights are
// integer; only w11=(x2-x1)*(y2-y1) can be nonzero, and it is 0 or 1.
// Returns (x1*S+y1)*C when weight==1, else -1 (row is zeros).
// ---------------------------------------------------------------------------
template <int S, int C>
__device__ __forceinline__ int level_offset(float h, float w) {
    constexpr float scale = (float)S / 224.0f;  // exact power of two
    float x = h * scale;
    float y = w * scale;
    int x1 = (int)floorf(x);
    int x2 = min((int)ceilf(x), S - 1);
    int y1 = (int)floorf(y);
    int y2 = min((int)ceilf(y), S - 1);
    return ((x2 > x1) && (y2 > y1)) ? (x1 * S + y1) * C : -1;
}

// Emit one level's C channels for one point. Warp-cooperative, float4,
// streaming stores (output never re-read; keep L2 for the feature scratch).
template <int C, int OFF>
__device__ __forceinline__ void emit(const float* __restrict__ fbuf,
                                     float* __restrict__ outrow,
                                     int off, int lane) {
    float4* dst = (float4*)(outrow + OFF);
    constexpr int N4 = C / 4;            // 16, 32, 64, 128
    constexpr int FULL = N4 / 32;        // warp-wide float4 iterations
    constexpr int REM = N4 - FULL * 32;  // remainder lanes

    if (off >= 0) {
        const float4* src = (const float4*)(fbuf + off);
#pragma unroll
        for (int i = 0; i < FULL; i++)
            __stcs(&dst[lane + 32 * i], __ldg(&src[lane + 32 * i]));
        if (REM > 0 && lane < REM)
            __stcs(&dst[FULL * 32 + lane], __ldg(&src[FULL * 32 + lane]));
    } else {
        const float4 z = make_float4(0.f, 0.f, 0.f, 0.f);
#pragma unroll
        for (int i = 0; i < FULL; i++)
            __stcs(&dst[lane + 32 * i], z);
        if (REM > 0 && lane < REM)
            __stcs(&dst[FULL * 32 + lane], z);
    }
}

// ---------------------------------------------------------------------------
// Main: each warp handles PTS_PER_WARP consecutive points. The pts slab for
// the warp (24 floats) is loaded coalesced by lanes 0..23 and redistributed
// via shuffles; lanes 0..7 then compute their own point's offsets. All offset
// math happens BEFORE cudaGridDependencySynchronize() so it overlaps the
// transpose kernel under programmatic dependent launch.
// ---------------------------------------------------------------------------
constexpr int PTS_PER_WARP = 8;

__global__ __launch_bounds__(256) void proj_kernel(const float* __restrict__ pts,
                                                   float* __restrict__ out,
                                                   int N) {
    int warp = (blockIdx.x * blockDim.x + threadIdx.x) >> 5;
    int lane = threadIdx.x & 31;
    int base = warp * PTS_PER_WARP;
    if (base >= N) return;

    // Coalesced load of this warp's 24 pts floats (pad-guarded).
    int nflt = min(N - base, PTS_PER_WARP) * 3;
    float v = (lane < nflt) ? __ldg(&pts[base * 3 + lane]) : 1.0f;

    // Lane l (< 8) owns point base+l: components at slab indices 3l, 3l+1, 3l+2.
    float px = __shfl_sync(0xFFFFFFFFu, v, 3 * (lane & 7) + 0);
    float py = __shfl_sync(0xFFFFFFFFu, v, 3 * (lane & 7) + 1);
    float pz = __shfl_sync(0xFFFFFFFFu, v, 3 * (lane & 7) + 2);

    int o0 = -1, o1 = -1, o2 = -1, o3 = -1;
    if (lane < PTS_PER_WARP && base + lane < N) {
        // Match XLA rounding exactly: no FMA contraction.
        float h = __fadd_rn(__fmul_rn(248.0f, __fdiv_rn(py, pz)), 111.5f);
        float w = __fadd_rn(__fmul_rn(248.0f, __fdiv_rn(px, -pz)), 111.5f);
        h = fminf(fmaxf(h, 0.0f), 223.0f);
        w = fminf(fmaxf(w, 0.0f), 223.0f);
        o0 = level_offset<56, 64>(h, w);
        o1 = level_offset<28, 128>(h, w);
        o2 = level_offset<14, 256>(h, w);
        o3 = level_offset<7, 512>(h, w);
    }

#if __CUDA_ARCH__ >= 900
    // Gate the g_f* reads on transpose completion (PDL).
    cudaGridDependencySynchronize();
#endif

#pragma unroll
    for (int i = 0; i < PTS_PER_WARP; i++) {
        int p = base + i;
        if (p >= N) break;
        float* outrow = out + (size_t)p * 960;
        int q0 = __shfl_sync(0xFFFFFFFFu, o0, i);
        int q1 = __shfl_sync(0xFFFFFFFFu, o1, i);
        int q2 = __shfl_sync(0xFFFFFFFFu, o2, i);
        int q3 = __shfl_sync(0xFFFFFFFFu, o3, i);
        emit<64, 0>(g_f0, outrow, q0, lane);
        emit<128, 64>(g_f1, outrow, q1, lane);
        emit<256, 192>(g_f2, outrow, q2, lane);
        emit<512, 448>(g_f3, outrow, q3, lane);
    }
}

extern "C" void kernel_launch(void* const* d_in, const int* in_sizes, int n_in,
                              void* d_out, int out_size) {
    const float* f0 = (const float*)d_in[0];
    const float* f1 = (const float*)d_in[1];
    const float* f2 = (const float*)d_in[2];
    const float* f3 = (const float*)d_in[3];
    const float* pts = (const float*)d_in[4];
    const int* batch = (const int*)d_in[5];

    int N = in_sizes[4] / 3;  // number of points

    dim3 tblock(32, 8);
    transpose_all_kernel<<<384, tblock>>>(f0, f1, f2, f3, batch);

    int warps = (N + PTS_PER_WARP - 1) / PTS_PER_WARP;
    int blocks = (warps * 32 + 255) / 256;

    // Launch proj with programmatic dependent launch so its prologue (pts
    // loads + offset math) overlaps the transpose kernel's tail.
    cudaLaunchConfig_t cfg = {};
    cfg.gridDim = dim3(blocks, 1, 1);
    cfg.blockDim = dim3(256, 1, 1);
    cfg.dynamicSmemBytes = 0;
    cfg.stream = 0;
    cudaLaunchAttribute attr[1];
    attr[0].id = cudaLaunchAttributeProgrammaticStreamSerialization;
    attr[0].val.programmaticStreamSerializationAllowed = 1;
    cfg.attrs = attr;
    cfg.numAttrs = 1;
    cudaError_t e = cudaLaunchKernelEx(&cfg, proj_kernel, pts, (float*)d_out, N);
    if (e != cudaSuccess) {
        // Fallback: plain launch (still correct, just serialized).
        proj_kernel<<<blocks, 256>>>(pts, (float*)d_out, N);
    }
}